// round 14
// baseline (speedup 1.0000x reference)
#include <cuda_runtime.h>
#include <stdint.h>
#include <math.h>

#define BB 32
#define PP 196
#define EE 2048
#define AA 512
#define DD 512
#define MMM 512
#define VV 10000
#define LLL 20
#define TTT 19
#define KCC 3072
#define G4 2048
#define NBIG 12560 /* fbeta | dec_att | fc */

#define OFF_PRED  0
#define OFF_CAPS  (BB*TTT*VV)
#define OFF_ALPHA (OFF_CAPS + BB*LLL)
#define OFF_SORT  (OFF_ALPHA + BB*TTT*PP)

#define COL_GATE 0
#define COL_ATT2 2048
#define COL_FC   2560

#define NBLK 444     /* 148 SMs x 3 blocks, co-resident */
#define NGRP 37      /* tree barrier: 37 groups x 12 */
#define GRPSZ 12

typedef unsigned long long ull;
typedef unsigned int u32;

// -------- scratch --------
__device__ float g_att1[BB*PP*AA];
__device__ float g_wcomb[KCC*G4 + 2048];
__device__ float g_wic[EE*1024 + 2048];
__device__ float g_wbig[DD*NBIG + 4096];
__device__ float g_mean[BB*EE];
__device__ float g_h[BB*DD];
__device__ float g_c[BB*DD];
__device__ float g_alpha[BB*PP];
__device__ float g_x2[BB*2048];
__device__ float g_part[24*BB*G4];
__device__ __align__(16) float g_part2[4*BB*NBIG];
__device__ int   g_sortind[BB];
__device__ int   g_declen[BB];
__device__ int   g_caps[BB*LLL];
__device__ u32   g_cnt1[NGRP*32];   // 128B-spaced leaf counters
__device__ u32   g_cnt2;
__device__ volatile u32 g_gen;

__device__ __forceinline__ float sigm(float x) { return 1.0f / (1.0f + expf(-x)); }

__device__ __forceinline__ ull ffma2(ull a, ull b, ull c) {
    ull d;
    asm("fma.rn.f32x2 %0, %1, %2, %3;" : "=l"(d) : "l"(a), "l"(b), "l"(c));
    return d;
}
__device__ __forceinline__ float pairsum(ull v) {
    float2 f = *reinterpret_cast<float2*>(&v);
    return f.x + f.y;
}
__device__ __forceinline__ ull dup2(float a) {
    ull r;
    asm("mov.b64 %0, {%1, %1};" : "=l"(r) : "f"(a));
    return r;
}
__device__ __forceinline__ void cp_async16(u32 smem_addr, const void* gptr) {
    asm volatile("cp.async.cg.shared.global [%0], [%1], 16;" :: "r"(smem_addr), "l"(gptr));
}
__device__ __forceinline__ void cp_commit() {
    asm volatile("cp.async.commit_group;" ::: "memory");
}
template<int N> __device__ __forceinline__ void cp_wait() {
    asm volatile("cp.async.wait_group %0;" :: "n"(N) : "memory");
}

// -------- tree grid barrier (444 = 37 groups of 12) --------------------------
__device__ __forceinline__ void grid_sync() {
    __syncthreads();
    if (threadIdx.x == 0) {
        u32 gen = g_gen;
        __threadfence();
        int g = blockIdx.x % NGRP;
        u32 r = atomicAdd(&g_cnt1[g * 32], 1u);
        if (r == GRPSZ - 1) {
            g_cnt1[g * 32] = 0;
            __threadfence();
            u32 r2 = atomicAdd(&g_cnt2, 1u);
            if (r2 == NGRP - 1) {
                g_cnt2 = 0;
                __threadfence();
                g_gen = gen + 1;
            }
        }
        while (g_gen == gen) { __nanosleep(32); }
        __threadfence();
    }
    __syncthreads();
}

// ============ cp.async skinny-GEMM body (KSEG=128), row-pointer X loader =====
__device__ __forceinline__ void gemm4r(
    float* Xs, float* Ws, const float* const* rowp,
    const float* __restrict__ Wp, int N2,
    float* __restrict__ part, int npad, int N,
    int chunk, int seg, int colOffset)
{
    const int KSEG = 128;
    int tid = threadIdx.x;
    int cg = tid & 63, bg = tid >> 6;
    int colbase = colOffset + chunk * 128;
    int kb = seg * KSEG;

    __syncthreads();   // rowp ready; prior users of Xs/Ws done

    #pragma unroll
    for (int i = 0; i < 4; ++i) {
        int f = i * 256 + tid;
        int r = f >> 5;
        int c4 = (f & 31) * 4;
        *reinterpret_cast<float4*>(&Xs[r * KSEG + c4]) =
            *reinterpret_cast<const float4*>(rowp[r] + c4);
    }

    const float* wsrc = Wp + (size_t)(kb >> 1) * N2 + (size_t)colbase * 2;
    u32 wsm = (u32)__cvta_generic_to_shared(Ws);
    const int NSB = 8;

    auto issue = [&](int sb) {
        if (sb < NSB) {
            const float* src = wsrc + (size_t)sb * 8 * N2;
            u32 dst = wsm + (u32)((sb % 3) * 2048 * 4);
            #pragma unroll
            for (int i = 0; i < 2; ++i) {
                int f = i * 256 + tid;
                int r = f >> 6;
                int c = (f & 63) << 2;
                cp_async16(dst + (u32)(r * 256 + c) * 4, src + (size_t)r * N2 + c);
            }
        }
        cp_commit();
    };
    issue(0); issue(1);
    __syncthreads();

    int j0 = colbase + cg, j1 = j0 + 64;
    bool v0 = (j0 < N), v1 = (j1 < N);
    int b0 = bg * 8;

    ull acc0[8], acc1[8];
    #pragma unroll
    for (int i = 0; i < 8; ++i) { acc0[i] = 0ull; acc1[i] = 0ull; }

    for (int sb = 0; sb < NSB; ++sb) {
        cp_wait<1>();
        __syncthreads();
        const float* W0 = Ws + (sb % 3) * 2048;
        int kk = sb * 16;
        #pragma unroll
        for (int kp2 = 0; kp2 < 4; ++kp2) {
            ull wa0 = *reinterpret_cast<const ull*>(W0 + (kp2*2    ) * 256 + cg * 2);
            ull wa1 = *reinterpret_cast<const ull*>(W0 + (kp2*2 + 1) * 256 + cg * 2);
            ull wb0 = *reinterpret_cast<const ull*>(W0 + (kp2*2    ) * 256 + 128 + cg * 2);
            ull wb1 = *reinterpret_cast<const ull*>(W0 + (kp2*2 + 1) * 256 + 128 + cg * 2);
            #pragma unroll
            for (int i = 0; i < 8; ++i) {
                ulonglong2 xv = *reinterpret_cast<const ulonglong2*>(&Xs[(b0 + i) * KSEG + kk + kp2 * 4]);
                acc0[i] = ffma2(xv.x, wa0, acc0[i]);
                acc0[i] = ffma2(xv.y, wa1, acc0[i]);
                acc1[i] = ffma2(xv.x, wb0, acc1[i]);
                acc1[i] = ffma2(xv.y, wb1, acc1[i]);
            }
        }
        __syncthreads();
        issue(sb + 2);
    }

    float* pp = part + ((size_t)seg * 32 + b0) * npad;
    #pragma unroll
    for (int i = 0; i < 8; ++i) {
        if (v0) pp[(size_t)i * npad + j0] = pairsum(acc0[i]);
        if (v1) pp[(size_t)i * npad + j1] = pairsum(acc1[i]);
    }
}

// -------- setup (also fully resets barrier state) ----------------------------
__global__ void k_setup(const int* __restrict__ lens, const int* __restrict__ caps_in,
                        float* __restrict__ out) {
    __shared__ int s_len[BB];
    __shared__ int s_si[BB];
    int tid = threadIdx.x;
    if (tid == 0) { g_cnt2 = 0; g_gen = 0; }
    for (int i = tid; i < NGRP*32; i += 32) g_cnt1[i] = 0;
    if (tid < BB) s_len[tid] = lens[tid];
    __syncthreads();
    if (tid < BB) {
        int li = s_len[tid];
        int r = 0;
        for (int j = 0; j < BB; ++j) {
            int lj = s_len[j];
            if (lj > li || (lj == li && j < tid)) r++;
        }
        s_si[r] = tid;
    }
    __syncthreads();
    if (tid < BB) {
        int si = s_si[tid];
        g_sortind[tid] = si;
        g_declen[tid]  = s_len[si] - 1;
        out[OFF_SORT + tid] = (float)si;
    }
    __syncthreads();
    for (int i = tid; i < BB*LLL; i += blockDim.x) {
        int b = i / LLL, w = i % LLL;
        int cv = caps_in[s_si[b]*LLL + w];
        g_caps[i] = cv;
        out[OFF_CAPS + i] = (float)cv;
    }
}

// -------- merged: att1 tiles [bid<392] + weight packing [bid>=392] -----------
#define PACK_TA ((long long)KCC * G4)
#define PACK_TB ((long long)DD * NBIG)
#define PACK_TC ((long long)EE * 1024)
#define PACK_TOTAL (PACK_TA + PACK_TB + PACK_TC)

__global__ __launch_bounds__(128, 3)
void k_att1_pack(const float* __restrict__ enc, const float* __restrict__ W,
                 const float* __restrict__ bias,
                 const float* __restrict__ W_ih, const float* __restrict__ W_hh,
                 const float* __restrict__ W_fc, const float* __restrict__ W_fbeta,
                 const float* __restrict__ W_dec,
                 const float* __restrict__ Wih0, const float* __restrict__ Wic0) {
    int bid = blockIdx.x;
    int tid = threadIdx.x;

    if (bid >= 392) {
        long long base = (long long)(bid - 392) * 1024;
        #pragma unroll
        for (int i = 0; i < 8; ++i) {
            long long idx = base + i * 128 + tid;
            if (idx >= PACK_TOTAL) return;
            if (idx < PACK_TA) {
                long long a = idx;
                int kp = (int)(a / (2*G4));
                int rem = (int)(a % (2*G4));
                int j = rem >> 1;
                int k = kp*2 + (rem & 1);
                float v = (k < 2560) ? W_ih[(size_t)j*2560 + k] : W_hh[(size_t)j*512 + (k - 2560)];
                g_wcomb[a] = v;
            } else if (idx < PACK_TA + PACK_TB) {
                long long b = idx - PACK_TA;
                int kp = (int)(b / (2*NBIG));
                int rem = (int)(b % (2*NBIG));
                int j = rem >> 1;
                int k = kp*2 + (rem & 1);
                float v;
                if (j < COL_ATT2)     v = W_fbeta[(size_t)k*EE + j];
                else if (j < COL_FC)  v = W_dec[(size_t)k*AA + (j - COL_ATT2)];
                else                  v = W_fc[(size_t)k*VV + (j - COL_FC)];
                g_wbig[b] = v;
            } else {
                long long c = idx - PACK_TA - PACK_TB;
                int kp = (int)(c >> 11);
                int rem = (int)(c & 2047);
                int j = rem >> 1;
                int k = kp*2 + (rem & 1);
                float v = (j < 512) ? Wih0[(size_t)k*512 + j] : Wic0[(size_t)k*512 + (j - 512)];
                g_wic[c] = v;
            }
        }
        return;
    }

    // ---- att1 tile: rowBase = (bid%49)*128, colBase = (bid/49)*64 ----
    __shared__ __align__(16) float As[16][128];
    __shared__ __align__(16) float Bs[16][64];
    int rowBase = (bid % 49) * 128;
    int colBase = (bid / 49) * 64;

    int grow = rowBase + tid;
    const float* asrc = enc + ((size_t)g_sortind[grow / PP] * PP + (grow % PP)) * EE;
    int bk0 = (tid >> 4) * 2;
    int bn  = (tid & 15) * 4;
    const float* bsrc = W + (size_t)bk0 * AA + colBase + bn;

    int m0 = (tid >> 3) * 8;
    int n0 = (tid & 7) * 8;

    ull acc[8][4];
    #pragma unroll
    for (int i = 0; i < 8; ++i)
        #pragma unroll
        for (int j = 0; j < 4; ++j) acc[i][j] = 0ull;

    float4 pa[4];
    #pragma unroll
    for (int u = 0; u < 4; ++u) pa[u] = *reinterpret_cast<const float4*>(asrc + 4*u);
    float4 pb0 = *reinterpret_cast<const float4*>(bsrc);
    float4 pb1 = *reinterpret_cast<const float4*>(bsrc + AA);

    for (int kb = 0; kb < EE; kb += 16) {
        #pragma unroll
        for (int u = 0; u < 4; ++u) {
            As[4*u + 0][tid] = pa[u].x;
            As[4*u + 1][tid] = pa[u].y;
            As[4*u + 2][tid] = pa[u].z;
            As[4*u + 3][tid] = pa[u].w;
        }
        *reinterpret_cast<float4*>(&Bs[bk0][bn])     = pb0;
        *reinterpret_cast<float4*>(&Bs[bk0 + 1][bn]) = pb1;
        __syncthreads();
        if (kb + 16 < EE) {
            #pragma unroll
            for (int u = 0; u < 4; ++u)
                pa[u] = *reinterpret_cast<const float4*>(asrc + kb + 16 + 4*u);
            pb0 = *reinterpret_cast<const float4*>(bsrc + (size_t)(kb + 16) * AA);
            pb1 = *reinterpret_cast<const float4*>(bsrc + (size_t)(kb + 17) * AA);
        }
        #pragma unroll
        for (int k = 0; k < 16; ++k) {
            float4 a0 = *reinterpret_cast<const float4*>(&As[k][m0]);
            float4 a1 = *reinterpret_cast<const float4*>(&As[k][m0 + 4]);
            ulonglong2 bp0 = *reinterpret_cast<const ulonglong2*>(&Bs[k][n0]);
            ulonglong2 bp1 = *reinterpret_cast<const ulonglong2*>(&Bs[k][n0 + 4]);
            float am[8] = {a0.x, a0.y, a0.z, a0.w, a1.x, a1.y, a1.z, a1.w};
            #pragma unroll
            for (int i = 0; i < 8; ++i) {
                ull ad = dup2(am[i]);
                acc[i][0] = ffma2(ad, bp0.x, acc[i][0]);
                acc[i][1] = ffma2(ad, bp0.y, acc[i][1]);
                acc[i][2] = ffma2(ad, bp1.x, acc[i][2]);
                acc[i][3] = ffma2(ad, bp1.y, acc[i][3]);
            }
        }
        __syncthreads();
    }
    float2 bb[4];
    #pragma unroll
    for (int jp = 0; jp < 4; ++jp)
        bb[jp] = *reinterpret_cast<const float2*>(bias + colBase + n0 + 2*jp);
    #pragma unroll
    for (int i = 0; i < 8; ++i) {
        int row = rowBase + m0 + i;
        #pragma unroll
        for (int jp = 0; jp < 4; ++jp) {
            float2 r = *reinterpret_cast<float2*>(&acc[i][jp]);
            float2 o = make_float2(r.x + bb[jp].x, r.y + bb[jp].y);
            *reinterpret_cast<float2*>(&g_att1[(size_t)row * AA + colBase + n0 + 2*jp]) = o;
        }
    }
}

// ================= persistent kernel: prologue tail + decode loop ============
__global__ __launch_bounds__(256, 3)
void k_loop(const float* __restrict__ enc, const float* __restrict__ emb,
            const float* __restrict__ b_dec, const float* __restrict__ W_full,
            const float* __restrict__ b_full, const float* __restrict__ b_fbeta,
            const float* __restrict__ b_ih, const float* __restrict__ b_hh,
            const float* __restrict__ b_fc, const float* __restrict__ b_init_h,
            const float* __restrict__ b_init_c, float* __restrict__ out) {
    __shared__ __align__(16) float Xs[32*128];     // 16 KB
    __shared__ __align__(16) float Ws[3*2048];     // 24 KB
    __shared__ const float* rowp[32];
    __shared__ __align__(16) float att2s[AA];
    __shared__ __align__(16) float wfs[AA];
    __shared__ float es[256];
    __shared__ float red[256];
    __shared__ float al[200];

    int tid = threadIdx.x;
    int bx = blockIdx.x;

    // ---- P1: mean (32 units) ----
    for (int unit = bx; unit < 32; unit += NBLK) {
        int b = unit;
        const float* base = enc + (size_t)g_sortind[b] * PP * EE;
        #pragma unroll
        for (int g = 0; g < 2; ++g) {
            int j = (tid * 2 + g) * 4;
            float4 s = make_float4(0.f, 0.f, 0.f, 0.f);
            #pragma unroll 4
            for (int p = 0; p < PP; ++p) {
                float4 v = *reinterpret_cast<const float4*>(base + (size_t)p * EE + j);
                s.x += v.x; s.y += v.y; s.z += v.z; s.w += v.w;
            }
            const float inv = 1.0f / 196.0f;
            s.x *= inv; s.y *= inv; s.z *= inv; s.w *= inv;
            *reinterpret_cast<float4*>(&g_mean[b*EE + j]) = s;
        }
    }
    grid_sync();

    // ---- P2: init GEMM (128 units: 8 chunks x 16 segs) ----
    for (int unit = bx; unit < 128; unit += NBLK) {
        int chunk = unit & 7, seg = unit >> 3;
        if (tid < 32) rowp[tid] = g_mean + tid * EE + seg * 128;
        gemm4r(Xs, Ws, rowp, g_wic, 2048, g_part, 1024, 1024, chunk, seg, 0);
    }
    grid_sync();

    // ---- P3: h0/c0 epilogue (64 units) ----
    for (int unit = bx; unit < 64; unit += NBLK) {
        int idx = unit * 256 + tid;
        int b = idx >> 9, d = idx & 511;
        float h = b_init_h[d], c = b_init_c[d];
        #pragma unroll
        for (int s = 0; s < 16; ++s) {
            h += g_part[(s*32 + b)*1024 + d];
            c += g_part[(s*32 + b)*1024 + 512 + d];
        }
        g_h[idx] = h;
        g_c[idx] = c;
    }
    grid_sync();

    // ---- P4: small0 (80 units) ----
    for (int unit = bx; unit < 80; unit += NBLK) {
        int chunk = unit % 20, seg = unit / 20;
        if (tid < 32) rowp[tid] = g_h + tid * DD + seg * 128;
        gemm4r(Xs, Ws, rowp, g_wbig, 2*NBIG, g_part2, NBIG, NBIG,
               chunk, seg, COL_GATE);
    }
    grid_sync();

    for (int t = 0; t < TTT; ++t) {
        // ---- Phase A: attn(t) [0..31] + fin(t-1) [32..351] -----------------
        {
            int nA = 32 + (t > 0 ? 320 : 0);
            for (int unit = bx; unit < nA; unit += NBLK) {
                if (unit < 32) {
                    int b = unit;
                    #pragma unroll
                    for (int cc = 0; cc < 2; ++cc) {
                        int c = tid + cc * 256;
                        float a2 = b_dec[c];
                        #pragma unroll
                        for (int s = 0; s < 4; ++s)
                            a2 += g_part2[((size_t)s * 32 + b) * NBIG + COL_ATT2 + c];
                        att2s[c] = a2;
                        wfs[c] = W_full[c];
                    }
                    __syncthreads();
                    int w = tid >> 5, lane = tid & 31;
                    float bf = b_full[0];
                    for (int p = w; p < PP; p += 8) {
                        const float4* row4 = reinterpret_cast<const float4*>(g_att1 + ((size_t)b * PP + p) * AA);
                        const float4* a24  = reinterpret_cast<const float4*>(att2s);
                        const float4* wf4  = reinterpret_cast<const float4*>(wfs);
                        float part = 0.0f;
                        #pragma unroll
                        for (int i = 0; i < 4; ++i) {
                            int a = lane + i * 32;
                            float4 v = row4[a];
                            float4 t2 = a24[a];
                            float4 wf = wf4[a];
                            part = fmaf(fmaxf(v.x + t2.x, 0.f), wf.x, part);
                            part = fmaf(fmaxf(v.y + t2.y, 0.f), wf.y, part);
                            part = fmaf(fmaxf(v.z + t2.z, 0.f), wf.z, part);
                            part = fmaf(fmaxf(v.w + t2.w, 0.f), wf.w, part);
                        }
                        #pragma unroll
                        for (int off = 16; off; off >>= 1)
                            part += __shfl_down_sync(0xffffffffu, part, off);
                        if (lane == 0) es[p] = part + bf;
                    }
                    __syncthreads();
                    float v = (tid < PP) ? es[tid] : -1e30f;
                    red[tid] = v; __syncthreads();
                    for (int s = 128; s > 0; s >>= 1) { if (tid < s) red[tid] = fmaxf(red[tid], red[tid+s]); __syncthreads(); }
                    float mx = red[0]; __syncthreads();
                    float ex = (tid < PP) ? expf(v - mx) : 0.0f;
                    red[tid] = ex; __syncthreads();
                    for (int s = 128; s > 0; s >>= 1) { if (tid < s) red[tid] += red[tid+s]; __syncthreads(); }
                    float inv = 1.0f / red[0];
                    __syncthreads();
                    if (tid < PP) {
                        float alpha = ex * inv;
                        g_alpha[b*PP + tid] = alpha;
                        float m = (g_declen[b] > t) ? 1.0f : 0.0f;
                        out[OFF_ALPHA + ((size_t)b*TTT + t)*PP + tid] = alpha * m;
                    }
                } else {
                    int q = unit - 32;
                    int b = q / 10;
                    int j = (q % 10) * 1024 + tid * 4;
                    int tprev = t - 1;
                    if (j < VV) {
                        float4 v = make_float4(0.f, 0.f, 0.f, 0.f);
                        if (g_declen[b] > tprev) {
                            v = *reinterpret_cast<const float4*>(b_fc + j);
                            #pragma unroll
                            for (int s = 0; s < 4; ++s) {
                                float4 p = *reinterpret_cast<const float4*>(
                                    &g_part2[((size_t)s * 32 + b) * NBIG + COL_FC + j]);
                                v.x += p.x; v.y += p.y; v.z += p.z; v.w += p.w;
                            }
                        }
                        *reinterpret_cast<float4*>(out + OFF_PRED + ((size_t)b*TTT + tprev)*VV + j) = v;
                    }
                }
            }
        }
        grid_sync();

        // ---- Phase B: stage — g_x2 = gate*awe (256 units) ------------------
        for (int unit = bx; unit < 256; unit += NBLK) {
            int b = unit >> 3;
            int j = (unit & 7) * 256 + tid;
            for (int i = tid; i < PP; i += 256) al[i] = g_alpha[b*PP + i];
            __syncthreads();
            int sb = g_sortind[b];
            const float* eb = enc + (size_t)sb * PP * EE + j;
            float awe0 = 0.f, awe1 = 0.f;
            #pragma unroll 8
            for (int p = 0; p < 192; p += 2) {
                awe0 = fmaf(al[p],     eb[(size_t)p * EE],       awe0);
                awe1 = fmaf(al[p + 1], eb[(size_t)(p + 1) * EE], awe1);
            }
            awe0 = fmaf(al[192], eb[(size_t)192 * EE], awe0);
            awe1 = fmaf(al[193], eb[(size_t)193 * EE], awe1);
            awe0 = fmaf(al[194], eb[(size_t)194 * EE], awe0);
            awe1 = fmaf(al[195], eb[(size_t)195 * EE], awe1);
            float awe = awe0 + awe1;
            float ga = b_fbeta[j];
            #pragma unroll
            for (int s = 0; s < 4; ++s)
                ga += g_part2[((size_t)s * 32 + b) * NBIG + COL_GATE + j];
            g_x2[b*2048 + j] = awe * sigm(ga);
            __syncthreads();
        }
        grid_sync();

        // ---- Phase C: gates(t) [384 units] ---------------------------------
        for (int unit = bx; unit < 384; unit += NBLK) {
            int chunk = unit & 15, seg = unit >> 4;
            if (tid < 32) {
                int kb = seg * 128;
                const float* p;
                if (seg < 4)       p = emb + (size_t)g_caps[tid*LLL + t] * MMM + kb;
                else if (seg < 20) p = g_x2 + tid * 2048 + (kb - 512);
                else               p = g_h + tid * DD + (kb - 2560);
                rowp[tid] = p;
            }
            gemm4r(Xs, Ws, rowp, g_wcomb, 2*G4, g_part, G4, G4, chunk, seg, 0);
        }
        grid_sync();

        // ---- Phase D: lstm(t) [64 units] -----------------------------------
        for (int unit = bx; unit < 64; unit += NBLK) {
            int idx = unit * 256 + tid;
            int b = idx >> 9, d = idx & 511;
            float s[4];
            #pragma unroll
            for (int g = 0; g < 4; ++g) {
                float acc = b_ih[g*512 + d] + b_hh[g*512 + d];
                #pragma unroll
                for (int seg = 0; seg < 24; ++seg)
                    acc += g_part[((size_t)seg * 32 + b) * G4 + g*512 + d];
                s[g] = acc;
            }
            float ig = sigm(s[0]), fg = sigm(s[1]), gg = tanhf(s[2]), og = sigm(s[3]);
            float cn = fg * g_c[idx] + ig * gg;
            float hn = og * tanhf(cn);
            if (g_declen[b] > t) { g_h[idx] = hn; g_c[idx] = cn; }
        }
        grid_sync();

        // ---- Phase E: small(t+1) [80 units, skip last] + preds(t) [316] ----
        {
            int nsmall = (t < TTT - 1) ? 80 : 0;
            int nE = nsmall + 316;
            for (int unit = bx; unit < nE; unit += NBLK) {
                if (unit < nsmall) {
                    int chunk = unit % 20, seg = unit / 20;
                    if (tid < 32) rowp[tid] = g_h + tid * DD + seg * 128;
                    gemm4r(Xs, Ws, rowp, g_wbig, 2*NBIG, g_part2, NBIG, NBIG,
                           chunk, seg, COL_GATE);
                } else {
                    int q = unit - nsmall;
                    int chunk = q % 79, seg = q / 79;
                    if (tid < 32) rowp[tid] = g_h + tid * DD + seg * 128;
                    gemm4r(Xs, Ws, rowp, g_wbig, 2*NBIG, g_part2, NBIG, NBIG,
                           chunk, seg, COL_FC);
                }
            }
        }
        grid_sync();
    }

    // ---- Tail: fin(18) (preds(18) partials from phase E of t=18) ------------
    for (int unit = bx; unit < 320; unit += NBLK) {
        int b = unit / 10;
        int j = (unit % 10) * 1024 + tid * 4;
        if (j < VV) {
            float4 v = make_float4(0.f, 0.f, 0.f, 0.f);
            if (g_declen[b] > TTT - 1) {
                v = *reinterpret_cast<const float4*>(b_fc + j);
                #pragma unroll
                for (int s = 0; s < 4; ++s) {
                    float4 p = *reinterpret_cast<const float4*>(
                        &g_part2[((size_t)s * 32 + b) * NBIG + COL_FC + j]);
                    v.x += p.x; v.y += p.y; v.z += p.z; v.w += p.w;
                }
            }
            *reinterpret_cast<float4*>(out + OFF_PRED + ((size_t)b*TTT + (TTT-1))*VV + j) = v;
        }
    }
}

// ============================================================================
extern "C" void kernel_launch(void* const* d_in, const int* in_sizes, int n_in,
                              void* d_out, int out_size) {
    const float* enc       = (const float*)d_in[0];
    const int*   caps_in   = (const int*)  d_in[1];
    const int*   lens      = (const int*)  d_in[2];
    const float* W_enc_att = (const float*)d_in[3];
    const float* b_enc_att = (const float*)d_in[4];
    const float* W_dec_att = (const float*)d_in[5];
    const float* b_dec_att = (const float*)d_in[6];
    const float* W_full    = (const float*)d_in[7];
    const float* b_full    = (const float*)d_in[8];
    const float* emb       = (const float*)d_in[9];
    const float* W_ih      = (const float*)d_in[10];
    const float* W_hh      = (const float*)d_in[11];
    const float* b_ih      = (const float*)d_in[12];
    const float* b_hh      = (const float*)d_in[13];
    const float* W_init_h  = (const float*)d_in[14];
    const float* b_init_h  = (const float*)d_in[15];
    const float* W_init_c  = (const float*)d_in[16];
    const float* b_init_c  = (const float*)d_in[17];
    const float* W_fbeta   = (const float*)d_in[18];
    const float* b_fbeta   = (const float*)d_in[19];
    const float* W_fc      = (const float*)d_in[20];
    const float* b_fc      = (const float*)d_in[21];
    float* out = (float*)d_out;

    const int packBlocks = (int)((PACK_TOTAL + 1023) / 1024);

    k_setup<<<1, 32>>>(lens, caps_in, out);
    k_att1_pack<<<392 + packBlocks, 128>>>(enc, W_enc_att, b_enc_att,
                                           W_ih, W_hh, W_fc, W_fbeta, W_dec_att,
                                           W_init_h, W_init_c);
    k_loop<<<NBLK, 256>>>(enc, emb, b_dec_att, W_full, b_full, b_fbeta,
                          b_ih, b_hh, b_fc, b_init_h, b_init_c, out);
    (void)in_sizes; (void)n_in; (void)out_size;
}

// round 15
// speedup vs baseline: 1.1004x; 1.1004x over previous
#include <cuda_runtime.h>
#include <stdint.h>
#include <math.h>

#define BB 32
#define PP 196
#define EE 2048
#define AA 512
#define DD 512
#define MMM 512
#define VV 10000
#define LLL 20
#define TTT 19
#define KCC 3072
#define G4 2048
#define NBIG 12560 /* fbeta | dec_att | fc */

#define OFF_PRED  0
#define OFF_CAPS  (BB*TTT*VV)
#define OFF_ALPHA (OFF_CAPS + BB*LLL)
#define OFF_SORT  (OFF_ALPHA + BB*TTT*PP)

#define COL_GATE 0
#define COL_ATT2 2048
#define COL_FC   2560

#define NBLK 444     /* 148 SMs x 3 blocks, co-resident */
#define NGRP 37      /* tree barrier: 37 groups x 12 */
#define GRPSZ 12

typedef unsigned long long ull;
typedef unsigned int u32;

// -------- scratch --------
__device__ float g_att1[BB*PP*AA];
__device__ float g_wcomb[KCC*G4 + 2048];
__device__ float g_wic[EE*1024 + 2048];
__device__ float g_wbig[DD*NBIG + 4096];
__device__ float g_mean[BB*EE];
__device__ float g_h[BB*DD];
__device__ float g_c[BB*DD];
__device__ float g_alpha[BB*PP];
__device__ float g_x2[BB*2048];
__device__ float g_part[24*BB*G4];
__device__ __align__(16) float g_part2[4*BB*NBIG];
__device__ int   g_sortind[BB];
__device__ int   g_declen[BB];
__device__ int   g_caps[BB*LLL];
__device__ u32   g_cnt1[NGRP*32];   // 128B-spaced leaf counters
__device__ u32   g_cnt2;
__device__ volatile u32 g_gen;

__device__ __forceinline__ float sigm(float x) { return 1.0f / (1.0f + expf(-x)); }

__device__ __forceinline__ ull ffma2(ull a, ull b, ull c) {
    ull d;
    asm("fma.rn.f32x2 %0, %1, %2, %3;" : "=l"(d) : "l"(a), "l"(b), "l"(c));
    return d;
}
__device__ __forceinline__ float pairsum(ull v) {
    float2 f = *reinterpret_cast<float2*>(&v);
    return f.x + f.y;
}
__device__ __forceinline__ ull dup2(float a) {
    ull r;
    asm("mov.b64 %0, {%1, %1};" : "=l"(r) : "f"(a));
    return r;
}
__device__ __forceinline__ void cp_async16(u32 smem_addr, const void* gptr) {
    asm volatile("cp.async.cg.shared.global [%0], [%1], 16;" :: "r"(smem_addr), "l"(gptr));
}
__device__ __forceinline__ void cp_commit() {
    asm volatile("cp.async.commit_group;" ::: "memory");
}
template<int N> __device__ __forceinline__ void cp_wait() {
    asm volatile("cp.async.wait_group %0;" :: "n"(N) : "memory");
}

// -------- tree grid barrier (444 = 37 groups of 12) --------------------------
__device__ __forceinline__ void grid_sync() {
    __syncthreads();
    if (threadIdx.x == 0) {
        u32 gen = g_gen;
        __threadfence();
        int g = blockIdx.x % NGRP;
        u32 r = atomicAdd(&g_cnt1[g * 32], 1u);
        if (r == GRPSZ - 1) {
            g_cnt1[g * 32] = 0;
            __threadfence();
            u32 r2 = atomicAdd(&g_cnt2, 1u);
            if (r2 == NGRP - 1) {
                g_cnt2 = 0;
                __threadfence();
                g_gen = gen + 1;
            }
        }
        while (g_gen == gen) { __nanosleep(32); }
        __threadfence();
    }
    __syncthreads();
}

// ============ cp.async skinny-GEMM body (KSEG=128), row-pointer X loader =====
// tthr: 8-row group (batch rows b0..b0+7, sorted by declen desc) is active iff
// g_declen[b0] > tthr. Inactive groups skip FMA + stores (consumers are masked).
// Pass tthr = -1 for always-active. Streaming + syncs stay block-uniform.
__device__ __forceinline__ void gemm4r(
    float* Xs, float* Ws, const float* const* rowp,
    const float* __restrict__ Wp, int N2,
    float* __restrict__ part, int npad, int N,
    int chunk, int seg, int colOffset, int tthr)
{
    const int KSEG = 128;
    int tid = threadIdx.x;
    int cg = tid & 63, bg = tid >> 6;
    int colbase = colOffset + chunk * 128;
    int kb = seg * KSEG;

    __syncthreads();   // rowp ready; prior users of Xs/Ws done

    #pragma unroll
    for (int i = 0; i < 4; ++i) {
        int f = i * 256 + tid;
        int r = f >> 5;
        int c4 = (f & 31) * 4;
        *reinterpret_cast<float4*>(&Xs[r * KSEG + c4]) =
            *reinterpret_cast<const float4*>(rowp[r] + c4);
    }

    const float* wsrc = Wp + (size_t)(kb >> 1) * N2 + (size_t)colbase * 2;
    u32 wsm = (u32)__cvta_generic_to_shared(Ws);
    const int NSB = 8;

    auto issue = [&](int sb) {
        if (sb < NSB) {
            const float* src = wsrc + (size_t)sb * 8 * N2;
            u32 dst = wsm + (u32)((sb % 3) * 2048 * 4);
            #pragma unroll
            for (int i = 0; i < 2; ++i) {
                int f = i * 256 + tid;
                int r = f >> 6;
                int c = (f & 63) << 2;
                cp_async16(dst + (u32)(r * 256 + c) * 4, src + (size_t)r * N2 + c);
            }
        }
        cp_commit();
    };
    issue(0); issue(1);
    __syncthreads();

    int j0 = colbase + cg, j1 = j0 + 64;
    bool v0 = (j0 < N), v1 = (j1 < N);
    int b0 = bg * 8;
    bool gactive = (tthr < 0) || (g_declen[b0] > tthr);

    ull acc0[8], acc1[8];
    #pragma unroll
    for (int i = 0; i < 8; ++i) { acc0[i] = 0ull; acc1[i] = 0ull; }

    for (int sb = 0; sb < NSB; ++sb) {
        cp_wait<1>();
        __syncthreads();
        if (gactive) {
            const float* W0 = Ws + (sb % 3) * 2048;
            int kk = sb * 16;
            #pragma unroll
            for (int kp2 = 0; kp2 < 4; ++kp2) {
                ull wa0 = *reinterpret_cast<const ull*>(W0 + (kp2*2    ) * 256 + cg * 2);
                ull wa1 = *reinterpret_cast<const ull*>(W0 + (kp2*2 + 1) * 256 + cg * 2);
                ull wb0 = *reinterpret_cast<const ull*>(W0 + (kp2*2    ) * 256 + 128 + cg * 2);
                ull wb1 = *reinterpret_cast<const ull*>(W0 + (kp2*2 + 1) * 256 + 128 + cg * 2);
                #pragma unroll
                for (int i = 0; i < 8; ++i) {
                    ulonglong2 xv = *reinterpret_cast<const ulonglong2*>(&Xs[(b0 + i) * KSEG + kk + kp2 * 4]);
                    acc0[i] = ffma2(xv.x, wa0, acc0[i]);
                    acc0[i] = ffma2(xv.y, wa1, acc0[i]);
                    acc1[i] = ffma2(xv.x, wb0, acc1[i]);
                    acc1[i] = ffma2(xv.y, wb1, acc1[i]);
                }
            }
        }
        __syncthreads();
        issue(sb + 2);
    }

    if (gactive) {
        float* pp = part + ((size_t)seg * 32 + b0) * npad;
        #pragma unroll
        for (int i = 0; i < 8; ++i) {
            if (v0) pp[(size_t)i * npad + j0] = pairsum(acc0[i]);
            if (v1) pp[(size_t)i * npad + j1] = pairsum(acc1[i]);
        }
    }
}

// -------- setup (also fully resets barrier state) ----------------------------
__global__ void k_setup(const int* __restrict__ lens, const int* __restrict__ caps_in,
                        float* __restrict__ out) {
    __shared__ int s_len[BB];
    __shared__ int s_si[BB];
    int tid = threadIdx.x;
    if (tid == 0) { g_cnt2 = 0; g_gen = 0; }
    for (int i = tid; i < NGRP*32; i += 32) g_cnt1[i] = 0;
    if (tid < BB) s_len[tid] = lens[tid];
    __syncthreads();
    if (tid < BB) {
        int li = s_len[tid];
        int r = 0;
        for (int j = 0; j < BB; ++j) {
            int lj = s_len[j];
            if (lj > li || (lj == li && j < tid)) r++;
        }
        s_si[r] = tid;
    }
    __syncthreads();
    if (tid < BB) {
        int si = s_si[tid];
        g_sortind[tid] = si;
        g_declen[tid]  = s_len[si] - 1;
        out[OFF_SORT + tid] = (float)si;
    }
    __syncthreads();
    for (int i = tid; i < BB*LLL; i += blockDim.x) {
        int b = i / LLL, w = i % LLL;
        int cv = caps_in[s_si[b]*LLL + w];
        g_caps[i] = cv;
        out[OFF_CAPS + i] = (float)cv;
    }
}

// -------- merged: att1 tiles [bid<392] + weight packing [bid>=392] -----------
#define PACK_TA ((long long)KCC * G4)
#define PACK_TB ((long long)DD * NBIG)
#define PACK_TC ((long long)EE * 1024)
#define PACK_TOTAL (PACK_TA + PACK_TB + PACK_TC)

__global__ __launch_bounds__(128, 3)
void k_att1_pack(const float* __restrict__ enc, const float* __restrict__ W,
                 const float* __restrict__ bias,
                 const float* __restrict__ W_ih, const float* __restrict__ W_hh,
                 const float* __restrict__ W_fc, const float* __restrict__ W_fbeta,
                 const float* __restrict__ W_dec,
                 const float* __restrict__ Wih0, const float* __restrict__ Wic0) {
    int bid = blockIdx.x;
    int tid = threadIdx.x;

    if (bid >= 392) {
        long long base = (long long)(bid - 392) * 1024;
        #pragma unroll
        for (int i = 0; i < 8; ++i) {
            long long idx = base + i * 128 + tid;
            if (idx >= PACK_TOTAL) return;
            if (idx < PACK_TA) {
                long long a = idx;
                int kp = (int)(a / (2*G4));
                int rem = (int)(a % (2*G4));
                int j = rem >> 1;
                int k = kp*2 + (rem & 1);
                float v = (k < 2560) ? W_ih[(size_t)j*2560 + k] : W_hh[(size_t)j*512 + (k - 2560)];
                g_wcomb[a] = v;
            } else if (idx < PACK_TA + PACK_TB) {
                long long b = idx - PACK_TA;
                int kp = (int)(b / (2*NBIG));
                int rem = (int)(b % (2*NBIG));
                int j = rem >> 1;
                int k = kp*2 + (rem & 1);
                float v;
                if (j < COL_ATT2)     v = W_fbeta[(size_t)k*EE + j];
                else if (j < COL_FC)  v = W_dec[(size_t)k*AA + (j - COL_ATT2)];
                else                  v = W_fc[(size_t)k*VV + (j - COL_FC)];
                g_wbig[b] = v;
            } else {
                long long c = idx - PACK_TA - PACK_TB;
                int kp = (int)(c >> 11);
                int rem = (int)(c & 2047);
                int j = rem >> 1;
                int k = kp*2 + (rem & 1);
                float v = (j < 512) ? Wih0[(size_t)k*512 + j] : Wic0[(size_t)k*512 + (j - 512)];
                g_wic[c] = v;
            }
        }
        return;
    }

    __shared__ __align__(16) float As[16][128];
    __shared__ __align__(16) float Bs[16][64];
    int rowBase = (bid % 49) * 128;
    int colBase = (bid / 49) * 64;

    int grow = rowBase + tid;
    const float* asrc = enc + ((size_t)g_sortind[grow / PP] * PP + (grow % PP)) * EE;
    int bk0 = (tid >> 4) * 2;
    int bn  = (tid & 15) * 4;
    const float* bsrc = W + (size_t)bk0 * AA + colBase + bn;

    int m0 = (tid >> 3) * 8;
    int n0 = (tid & 7) * 8;

    ull acc[8][4];
    #pragma unroll
    for (int i = 0; i < 8; ++i)
        #pragma unroll
        for (int j = 0; j < 4; ++j) acc[i][j] = 0ull;

    float4 pa[4];
    #pragma unroll
    for (int u = 0; u < 4; ++u) pa[u] = *reinterpret_cast<const float4*>(asrc + 4*u);
    float4 pb0 = *reinterpret_cast<const float4*>(bsrc);
    float4 pb1 = *reinterpret_cast<const float4*>(bsrc + AA);

    for (int kb = 0; kb < EE; kb += 16) {
        #pragma unroll
        for (int u = 0; u < 4; ++u) {
            As[4*u + 0][tid] = pa[u].x;
            As[4*u + 1][tid] = pa[u].y;
            As[4*u + 2][tid] = pa[u].z;
            As[4*u + 3][tid] = pa[u].w;
        }
        *reinterpret_cast<float4*>(&Bs[bk0][bn])     = pb0;
        *reinterpret_cast<float4*>(&Bs[bk0 + 1][bn]) = pb1;
        __syncthreads();
        if (kb + 16 < EE) {
            #pragma unroll
            for (int u = 0; u < 4; ++u)
                pa[u] = *reinterpret_cast<const float4*>(asrc + kb + 16 + 4*u);
            pb0 = *reinterpret_cast<const float4*>(bsrc + (size_t)(kb + 16) * AA);
            pb1 = *reinterpret_cast<const float4*>(bsrc + (size_t)(kb + 17) * AA);
        }
        #pragma unroll
        for (int k = 0; k < 16; ++k) {
            float4 a0 = *reinterpret_cast<const float4*>(&As[k][m0]);
            float4 a1 = *reinterpret_cast<const float4*>(&As[k][m0 + 4]);
            ulonglong2 bp0 = *reinterpret_cast<const ulonglong2*>(&Bs[k][n0]);
            ulonglong2 bp1 = *reinterpret_cast<const ulonglong2*>(&Bs[k][n0 + 4]);
            float am[8] = {a0.x, a0.y, a0.z, a0.w, a1.x, a1.y, a1.z, a1.w};
            #pragma unroll
            for (int i = 0; i < 8; ++i) {
                ull ad = dup2(am[i]);
                acc[i][0] = ffma2(ad, bp0.x, acc[i][0]);
                acc[i][1] = ffma2(ad, bp0.y, acc[i][1]);
                acc[i][2] = ffma2(ad, bp1.x, acc[i][2]);
                acc[i][3] = ffma2(ad, bp1.y, acc[i][3]);
            }
        }
        __syncthreads();
    }
    float2 bb[4];
    #pragma unroll
    for (int jp = 0; jp < 4; ++jp)
        bb[jp] = *reinterpret_cast<const float2*>(bias + colBase + n0 + 2*jp);
    #pragma unroll
    for (int i = 0; i < 8; ++i) {
        int row = rowBase + m0 + i;
        #pragma unroll
        for (int jp = 0; jp < 4; ++jp) {
            float2 r = *reinterpret_cast<float2*>(&acc[i][jp]);
            float2 o = make_float2(r.x + bb[jp].x, r.y + bb[jp].y);
            *reinterpret_cast<float2*>(&g_att1[(size_t)row * AA + colBase + n0 + 2*jp]) = o;
        }
    }
}

// ================= persistent kernel: prologue tail + decode loop ============
__global__ __launch_bounds__(256, 3)
void k_loop(const float* __restrict__ enc, const float* __restrict__ emb,
            const float* __restrict__ b_dec, const float* __restrict__ W_full,
            const float* __restrict__ b_full, const float* __restrict__ b_fbeta,
            const float* __restrict__ b_ih, const float* __restrict__ b_hh,
            const float* __restrict__ b_fc, const float* __restrict__ b_init_h,
            const float* __restrict__ b_init_c, float* __restrict__ out) {
    __shared__ __align__(16) float Xs[32*128];
    __shared__ __align__(16) float Ws[3*2048];
    __shared__ const float* rowp[32];
    __shared__ __align__(16) float att2s[AA];
    __shared__ __align__(16) float wfs[AA];
    __shared__ float es[256];
    __shared__ float red[256];
    __shared__ float al[200];

    int tid = threadIdx.x;
    int bx = blockIdx.x;

    // ---- P1: mean (32 units) ----
    for (int unit = bx; unit < 32; unit += NBLK) {
        int b = unit;
        const float* base = enc + (size_t)g_sortind[b] * PP * EE;
        #pragma unroll
        for (int g = 0; g < 2; ++g) {
            int j = (tid * 2 + g) * 4;
            float4 s = make_float4(0.f, 0.f, 0.f, 0.f);
            #pragma unroll 4
            for (int p = 0; p < PP; ++p) {
                float4 v = *reinterpret_cast<const float4*>(base + (size_t)p * EE + j);
                s.x += v.x; s.y += v.y; s.z += v.z; s.w += v.w;
            }
            const float inv = 1.0f / 196.0f;
            s.x *= inv; s.y *= inv; s.z *= inv; s.w *= inv;
            *reinterpret_cast<float4*>(&g_mean[b*EE + j]) = s;
        }
    }
    grid_sync();

    // ---- P2: init GEMM (128 units) ----
    for (int unit = bx; unit < 128; unit += NBLK) {
        int chunk = unit & 7, seg = unit >> 3;
        if (tid < 32) rowp[tid] = g_mean + tid * EE + seg * 128;
        gemm4r(Xs, Ws, rowp, g_wic, 2048, g_part, 1024, 1024, chunk, seg, 0, -1);
    }
    grid_sync();

    // ---- P3: h0/c0 epilogue (64 units) ----
    for (int unit = bx; unit < 64; unit += NBLK) {
        int idx = unit * 256 + tid;
        int b = idx >> 9, d = idx & 511;
        float h = b_init_h[d], c = b_init_c[d];
        #pragma unroll
        for (int s = 0; s < 16; ++s) {
            h += g_part[(s*32 + b)*1024 + d];
            c += g_part[(s*32 + b)*1024 + 512 + d];
        }
        g_h[idx] = h;
        g_c[idx] = c;
    }
    grid_sync();

    // ---- P4: small0 (80 units) ----
    for (int unit = bx; unit < 80; unit += NBLK) {
        int chunk = unit % 20, seg = unit / 20;
        if (tid < 32) rowp[tid] = g_h + tid * DD + seg * 128;
        gemm4r(Xs, Ws, rowp, g_wbig, 2*NBIG, g_part2, NBIG, NBIG,
               chunk, seg, COL_GATE, -1);
    }
    grid_sync();

    for (int t = 0; t < TTT; ++t) {
        // ---- Phase A: attn(t) [0..31] + fin(t-1) [32..351] -----------------
        {
            int nA = 32 + (t > 0 ? 320 : 0);
            for (int unit = bx; unit < nA; unit += NBLK) {
                if (unit < 32) {
                    int b = unit;
                    if (g_declen[b] <= t) {
                        // inactive row: output alphas are masked to 0; skip compute
                        if (tid < PP)
                            out[OFF_ALPHA + ((size_t)b*TTT + t)*PP + tid] = 0.0f;
                        continue;
                    }
                    #pragma unroll
                    for (int cc = 0; cc < 2; ++cc) {
                        int c = tid + cc * 256;
                        float a2 = b_dec[c];
                        #pragma unroll
                        for (int s = 0; s < 4; ++s)
                            a2 += g_part2[((size_t)s * 32 + b) * NBIG + COL_ATT2 + c];
                        att2s[c] = a2;
                        wfs[c] = W_full[c];
                    }
                    __syncthreads();
                    int w = tid >> 5, lane = tid & 31;
                    float bf = b_full[0];
                    for (int p = w; p < PP; p += 8) {
                        const float4* row4 = reinterpret_cast<const float4*>(g_att1 + ((size_t)b * PP + p) * AA);
                        const float4* a24  = reinterpret_cast<const float4*>(att2s);
                        const float4* wf4  = reinterpret_cast<const float4*>(wfs);
                        float part = 0.0f;
                        #pragma unroll
                        for (int i = 0; i < 4; ++i) {
                            int a = lane + i * 32;
                            float4 v = row4[a];
                            float4 t2 = a24[a];
                            float4 wf = wf4[a];
                            part = fmaf(fmaxf(v.x + t2.x, 0.f), wf.x, part);
                            part = fmaf(fmaxf(v.y + t2.y, 0.f), wf.y, part);
                            part = fmaf(fmaxf(v.z + t2.z, 0.f), wf.z, part);
                            part = fmaf(fmaxf(v.w + t2.w, 0.f), wf.w, part);
                        }
                        #pragma unroll
                        for (int off = 16; off; off >>= 1)
                            part += __shfl_down_sync(0xffffffffu, part, off);
                        if (lane == 0) es[p] = part + bf;
                    }
                    __syncthreads();
                    float v = (tid < PP) ? es[tid] : -1e30f;
                    red[tid] = v; __syncthreads();
                    for (int s = 128; s > 0; s >>= 1) { if (tid < s) red[tid] = fmaxf(red[tid], red[tid+s]); __syncthreads(); }
                    float mx = red[0]; __syncthreads();
                    float ex = (tid < PP) ? expf(v - mx) : 0.0f;
                    red[tid] = ex; __syncthreads();
                    for (int s = 128; s > 0; s >>= 1) { if (tid < s) red[tid] += red[tid+s]; __syncthreads(); }
                    float inv = 1.0f / red[0];
                    __syncthreads();
                    if (tid < PP) {
                        float alpha = ex * inv;
                        g_alpha[b*PP + tid] = alpha;
                        out[OFF_ALPHA + ((size_t)b*TTT + t)*PP + tid] = alpha;
                    }
                } else {
                    int q = unit - 32;
                    int b = q / 10;
                    int j = (q % 10) * 1024 + tid * 4;
                    int tprev = t - 1;
                    if (j < VV) {
                        float4 v = make_float4(0.f, 0.f, 0.f, 0.f);
                        if (g_declen[b] > tprev) {
                            v = *reinterpret_cast<const float4*>(b_fc + j);
                            #pragma unroll
                            for (int s = 0; s < 4; ++s) {
                                float4 p = *reinterpret_cast<const float4*>(
                                    &g_part2[((size_t)s * 32 + b) * NBIG + COL_FC + j]);
                                v.x += p.x; v.y += p.y; v.z += p.z; v.w += p.w;
                            }
                        }
                        *reinterpret_cast<float4*>(out + OFF_PRED + ((size_t)b*TTT + tprev)*VV + j) = v;
                    }
                }
            }
        }
        grid_sync();

        // ---- Phase B: stage (256 units; skip inactive rows) ----------------
        for (int unit = bx; unit < 256; unit += NBLK) {
            int b = unit >> 3;
            if (g_declen[b] <= t) continue;      // uniform per block-unit
            int j = (unit & 7) * 256 + tid;
            for (int i = tid; i < PP; i += 256) al[i] = g_alpha[b*PP + i];
            __syncthreads();
            int sb = g_sortind[b];
            const float* eb = enc + (size_t)sb * PP * EE + j;
            float awe0 = 0.f, awe1 = 0.f;
            #pragma unroll 8
            for (int p = 0; p < 192; p += 2) {
                awe0 = fmaf(al[p],     eb[(size_t)p * EE],       awe0);
                awe1 = fmaf(al[p + 1], eb[(size_t)(p + 1) * EE], awe1);
            }
            awe0 = fmaf(al[192], eb[(size_t)192 * EE], awe0);
            awe1 = fmaf(al[193], eb[(size_t)193 * EE], awe1);
            awe0 = fmaf(al[194], eb[(size_t)194 * EE], awe0);
            awe1 = fmaf(al[195], eb[(size_t)195 * EE], awe1);
            float awe = awe0 + awe1;
            float ga = b_fbeta[j];
            #pragma unroll
            for (int s = 0; s < 4; ++s)
                ga += g_part2[((size_t)s * 32 + b) * NBIG + COL_GATE + j];
            g_x2[b*2048 + j] = awe * sigm(ga);
            __syncthreads();
        }
        grid_sync();

        // ---- Phase C: gates(t) [384 units; group skip via tthr=t] ----------
        for (int unit = bx; unit < 384; unit += NBLK) {
            int chunk = unit & 15, seg = unit >> 4;
            if (tid < 32) {
                int kb = seg * 128;
                const float* p;
                if (seg < 4)       p = emb + (size_t)g_caps[tid*LLL + t] * MMM + kb;
                else if (seg < 20) p = g_x2 + tid * 2048 + (kb - 512);
                else               p = g_h + tid * DD + (kb - 2560);
                rowp[tid] = p;
            }
            gemm4r(Xs, Ws, rowp, g_wcomb, 2*G4, g_part, G4, G4, chunk, seg, 0, t);
        }
        grid_sync();

        // ---- Phase D: lstm(t) [64 units; skip inactive rows] ---------------
        for (int unit = bx; unit < 64; unit += NBLK) {
            int idx = unit * 256 + tid;
            int b = idx >> 9, d = idx & 511;
            if (g_declen[b] <= t) continue;      // b uniform per half-warp group; no syncs below
            float s[4];
            #pragma unroll
            for (int g = 0; g < 4; ++g) {
                float acc = b_ih[g*512 + d] + b_hh[g*512 + d];
                #pragma unroll
                for (int seg = 0; seg < 24; ++seg)
                    acc += g_part[((size_t)seg * 32 + b) * G4 + g*512 + d];
                s[g] = acc;
            }
            float ig = sigm(s[0]), fg = sigm(s[1]), gg = tanhf(s[2]), og = sigm(s[3]);
            float cn = fg * g_c[idx] + ig * gg;
            float hn = og * tanhf(cn);
            g_h[idx] = hn; g_c[idx] = cn;
        }
        grid_sync();

        // ---- Phase E: small(t+1) [80; tthr=t+1] + preds(t) [316; tthr=t] ---
        {
            int nsmall = (t < TTT - 1) ? 80 : 0;
            int nE = nsmall + 316;
            for (int unit = bx; unit < nE; unit += NBLK) {
                if (unit < nsmall) {
                    int chunk = unit % 20, seg = unit / 20;
                    if (tid < 32) rowp[tid] = g_h + tid * DD + seg * 128;
                    gemm4r(Xs, Ws, rowp, g_wbig, 2*NBIG, g_part2, NBIG, NBIG,
                           chunk, seg, COL_GATE, t + 1);
                } else {
                    int q = unit - nsmall;
                    int chunk = q % 79, seg = q / 79;
                    if (tid < 32) rowp[tid] = g_h + tid * DD + seg * 128;
                    gemm4r(Xs, Ws, rowp, g_wbig, 2*NBIG, g_part2, NBIG, NBIG,
                           chunk, seg, COL_FC, t);
                }
            }
        }
        grid_sync();
    }

    // ---- Tail: fin(18) ------------------------------------------------------
    for (int unit = bx; unit < 320; unit += NBLK) {
        int b = unit / 10;
        int j = (unit % 10) * 1024 + tid * 4;
        if (j < VV) {
            float4 v = make_float4(0.f, 0.f, 0.f, 0.f);
            if (g_declen[b] > TTT - 1) {
                v = *reinterpret_cast<const float4*>(b_fc + j);
                #pragma unroll
                for (int s = 0; s < 4; ++s) {
                    float4 p = *reinterpret_cast<const float4*>(
                        &g_part2[((size_t)s * 32 + b) * NBIG + COL_FC + j]);
                    v.x += p.x; v.y += p.y; v.z += p.z; v.w += p.w;
                }
            }
            *reinterpret_cast<float4*>(out + OFF_PRED + ((size_t)b*TTT + (TTT-1))*VV + j) = v;
        }
    }
}

// ============================================================================
extern "C" void kernel_launch(void* const* d_in, const int* in_sizes, int n_in,
                              void* d_out, int out_size) {
    const float* enc       = (const float*)d_in[0];
    const int*   caps_in   = (const int*)  d_in[1];
    const int*   lens      = (const int*)  d_in[2];
    const float* W_enc_att = (const float*)d_in[3];
    const float* b_enc_att = (const float*)d_in[4];
    const float* W_dec_att = (const float*)d_in[5];
    const float* b_dec_att = (const float*)d_in[6];
    const float* W_full    = (const float*)d_in[7];
    const float* b_full    = (const float*)d_in[8];
    const float* emb       = (const float*)d_in[9];
    const float* W_ih      = (const float*)d_in[10];
    const float* W_hh      = (const float*)d_in[11];
    const float* b_ih      = (const float*)d_in[12];
    const float* b_hh      = (const float*)d_in[13];
    const float* W_init_h  = (const float*)d_in[14];
    const float* b_init_h  = (const float*)d_in[15];
    const float* W_init_c  = (const float*)d_in[16];
    const float* b_init_c  = (const float*)d_in[17];
    const float* W_fbeta   = (const float*)d_in[18];
    const float* b_fbeta   = (const float*)d_in[19];
    const float* W_fc      = (const float*)d_in[20];
    const float* b_fc      = (const float*)d_in[21];
    float* out = (float*)d_out;

    const int packBlocks = (int)((PACK_TOTAL + 1023) / 1024);

    k_setup<<<1, 32>>>(lens, caps_in, out);
    k_att1_pack<<<392 + packBlocks, 128>>>(enc, W_enc_att, b_enc_att,
                                           W_ih, W_hh, W_fc, W_fbeta, W_dec_att,
                                           W_init_h, W_init_c);
    k_loop<<<NBLK, 256>>>(enc, emb, b_dec_att, W_full, b_full, b_fbeta,
                          b_ih, b_hh, b_fc, b_init_h, b_init_c, out);
    (void)in_sizes; (void)n_in; (void)out_size;
}